// round 1
// baseline (speedup 1.0000x reference)
#include <cuda_runtime.h>
#include <cuda_bf16.h>

// Problem constants
// B=1024, N_N=N_A=96, D=512, D2=256, D4=128
#define BATCH 1024
#define NN 96
#define DIM 512
#define D2 256
#define D4 128

// Scratch layout (single __device__ array; no allocations allowed)
#define OFF_PRE 0                        // [1024][512]  img@W1_top + b1
#define OFF_T   (OFF_PRE + BATCH*DIM)    // [2][96][512] text@W1_bot
#define OFF_E   (OFF_T + 2*NN*DIM)       // [2][1024][96] exp(softmax(sims))
#define OFF_S2  (OFF_E + 2*BATCH*NN)     // [2][1024][256] sum_n relu(h1@W2+b2)
#define SCRATCH_TOTAL (OFF_S2 + 2*BATCH*D2)

__device__ float g_scratch[SCRATCH_TOTAL];

// ---------------------------------------------------------------------------
// K1: sims = scale * img@text^T, per-branch softmax, E = exp(softmax)
// Block handles 8 batch rows; 256 threads.
// ---------------------------------------------------------------------------
__global__ void __launch_bounds__(256) k_softmax(
    const float* __restrict__ img, const float* __restrict__ tn,
    const float* __restrict__ ta, const float* __restrict__ ls)
{
    __shared__ float imgs[8][DIM];
    __shared__ float sims[8][192];
    const int b0 = blockIdx.x * 8;
    const int t = threadIdx.x;

    // load 8 image rows (coalesced float4)
    const float4* gi = (const float4*)(img + (size_t)b0 * DIM);
    float4* si = (float4*)&imgs[0][0];
    for (int i = t; i < 8 * (DIM / 4); i += 256) si[i] = gi[i];
    __syncthreads();

    const float scale = expf(ls[0]);

    // 192 dots (96 normal + 96 abnormal) x 8 batch rows; thread t owns text row t
    if (t < 192) {
        const float* txt = (t < 96) ? (tn + (size_t)t * DIM) : (ta + (size_t)(t - 96) * DIM);
        const float4* tv = (const float4*)txt;
        float acc[8];
        #pragma unroll
        for (int bi = 0; bi < 8; bi++) acc[bi] = 0.f;
        for (int k = 0; k < DIM / 4; k++) {
            float4 x = tv[k];
            #pragma unroll
            for (int bi = 0; bi < 8; bi++) {
                float4 y = *(const float4*)&imgs[bi][k * 4];
                acc[bi] += x.x * y.x + x.y * y.y + x.z * y.z + x.w * y.w;
            }
        }
        #pragma unroll
        for (int bi = 0; bi < 8; bi++) sims[bi][t] = acc[bi] * scale;
    }
    __syncthreads();

    // warp w handles batch row b0+w; 96 values = 3 per lane
    const int w = t >> 5, lane = t & 31;
    const int b = b0 + w;
    #pragma unroll
    for (int br = 0; br < 2; br++) {
        float v0 = sims[w][br * 96 + lane];
        float v1 = sims[w][br * 96 + lane + 32];
        float v2 = sims[w][br * 96 + lane + 64];
        float m = fmaxf(v0, fmaxf(v1, v2));
        #pragma unroll
        for (int off = 16; off > 0; off >>= 1)
            m = fmaxf(m, __shfl_xor_sync(0xffffffffu, m, off));
        float e0 = expf(v0 - m), e1 = expf(v1 - m), e2 = expf(v2 - m);
        float s = e0 + e1 + e2;
        #pragma unroll
        for (int off = 16; off > 0; off >>= 1)
            s += __shfl_xor_sync(0xffffffffu, s, off);
        float inv = 1.f / s;
        float* Eo = g_scratch + OFF_E + ((size_t)br * BATCH + b) * NN;
        Eo[lane]      = expf(e0 * inv);
        Eo[lane + 32] = expf(e1 * inv);
        Eo[lane + 64] = expf(e2 * inv);
    }
}

// ---------------------------------------------------------------------------
// K2/K3: generic fp32 GEMM  C[m][n] = A[m][k] @ Bm[k][n] (+ bias[n])
// C written into g_scratch + coff. 64x64 tile, BK=16, 256 threads, 4x4 micro.
// ---------------------------------------------------------------------------
__global__ void __launch_bounds__(256) k_gemm(
    const float* __restrict__ A, const float* __restrict__ Bm,
    const float* __restrict__ bias, int coff, int M, int N, int K)
{
    __shared__ float As[16][64];
    __shared__ float Bs[16][64];
    float* C = g_scratch + coff;
    const int n0 = blockIdx.x * 64, m0 = blockIdx.y * 64;
    const int t = threadIdx.x;
    const int tx = t & 15, ty = t >> 4;

    float acc[4][4];
    #pragma unroll
    for (int i = 0; i < 4; i++)
        #pragma unroll
        for (int j = 0; j < 4; j++) acc[i][j] = 0.f;

    for (int k0 = 0; k0 < K; k0 += 16) {
        __syncthreads();
        {
            int aRow = t >> 2, aCol = (t & 3) * 4;
            float4 v = make_float4(0.f, 0.f, 0.f, 0.f);
            if (m0 + aRow < M)
                v = *(const float4*)&A[(size_t)(m0 + aRow) * K + k0 + aCol];
            As[aCol][aRow] = v.x; As[aCol + 1][aRow] = v.y;
            As[aCol + 2][aRow] = v.z; As[aCol + 3][aRow] = v.w;
            int bRow = t >> 4, bCol = (t & 15) * 4;
            float4 wv = *(const float4*)&Bm[(size_t)(k0 + bRow) * N + n0 + bCol];
            *(float4*)&Bs[bRow][bCol] = wv;
        }
        __syncthreads();
        #pragma unroll
        for (int kk = 0; kk < 16; kk++) {
            float4 a = *(const float4*)&As[kk][ty * 4];
            float4 bq = *(const float4*)&Bs[kk][tx * 4];
            float av[4] = {a.x, a.y, a.z, a.w};
            float bv[4] = {bq.x, bq.y, bq.z, bq.w};
            #pragma unroll
            for (int i = 0; i < 4; i++)
                #pragma unroll
                for (int j = 0; j < 4; j++) acc[i][j] += av[i] * bv[j];
        }
    }
    #pragma unroll
    for (int i = 0; i < 4; i++) {
        int m = m0 + ty * 4 + i;
        if (m < M) {
            #pragma unroll
            for (int j = 0; j < 4; j++) {
                int n = n0 + tx * 4 + j;
                float bb = bias ? bias[n] : 0.f;
                C[(size_t)m * N + n] = acc[i][j] + bb;
            }
        }
    }
}

// ---------------------------------------------------------------------------
// K4: fused step 2.  For branch beta, batch tile of 4:
//   S2[b,c] = sum_{n=0..95} relu( sum_j relu(Pre[b,j] + e[b,n]*T[n,j]) * W2[j,c] + b2[c] )
// h1 built in SMEM per 128-wide K chunk; GEMM via packed fma.rn.f32x2.
// 256 threads; thread = output column c; 64 rows (4b x 16n) as 32 f32x2 accs.
// ---------------------------------------------------------------------------
#define S2_BT 4
#define S2_NT 16
#define S2_KC 128

__global__ void __launch_bounds__(256, 2) k_step2(
    const float* __restrict__ W2, const float* __restrict__ b2)
{
    __shared__ float Pre_s[S2_BT][S2_KC + 1];
    __shared__ float T_s[S2_NT][S2_KC + 1];
    __shared__ float h1_s[S2_KC][S2_BT * S2_NT];   // [j][row], row = bi*16+ni
    __shared__ float e_s[S2_BT * S2_NT];

    const int c = threadIdx.x;              // 0..255 output column
    const int beta = blockIdx.y;
    const int b0 = blockIdx.x * S2_BT;

    const float* Pre = g_scratch + OFF_PRE + (size_t)b0 * DIM;
    const float* T   = g_scratch + OFF_T + (size_t)beta * NN * DIM;
    const float* E   = g_scratch + OFF_E + ((size_t)beta * BATCH + b0) * NN;

    float S2a[S2_BT] = {0.f, 0.f, 0.f, 0.f};
    const float b2c = b2[c];

    for (int n0 = 0; n0 < NN; n0 += S2_NT) {
        unsigned long long acc[32];
        #pragma unroll
        for (int p = 0; p < 32; p++) acc[p] = 0ULL;  // (0.0f, 0.0f)

        for (int k0 = 0; k0 < DIM; k0 += S2_KC) {
            __syncthreads();
            if (c < 64)
                e_s[c] = E[(size_t)(c >> 4) * NN + n0 + (c & 15)];
            for (int i = c; i < S2_BT * S2_KC; i += 256) {
                int bi = i >> 7, jj = i & 127;
                Pre_s[bi][jj] = Pre[(size_t)bi * DIM + k0 + jj];
            }
            for (int i = c; i < S2_NT * S2_KC; i += 256) {
                int ni = i >> 7, jj = i & 127;
                T_s[ni][jj] = T[(size_t)(n0 + ni) * DIM + k0 + jj];
            }
            __syncthreads();
            // build h1 chunk
            for (int i = c; i < S2_KC * 64; i += 256) {
                int jj = i >> 6, row = i & 63;
                float v = Pre_s[row >> 4][jj] + e_s[row] * T_s[row & 15][jj];
                h1_s[jj][row] = fmaxf(v, 0.f);
            }
            __syncthreads();
            // GEMM over this K chunk: acc[rows] += h1[jj][rows] * W2[k0+jj][c]
            const float* w2p = W2 + (size_t)k0 * D2 + c;
            float w = __ldg(w2p);
            #pragma unroll 2
            for (int jj = 0; jj < S2_KC; jj++) {
                float wn = (jj + 1 < S2_KC) ? __ldg(w2p + (size_t)(jj + 1) * D2) : 0.f;
                unsigned long long wp;
                unsigned int wu = __float_as_uint(w);
                asm("mov.b64 %0, {%1, %1};" : "=l"(wp) : "r"(wu));
                const ulonglong2* hp = (const ulonglong2*)(&h1_s[jj][0]);
                #pragma unroll
                for (int q = 0; q < 16; q++) {
                    ulonglong2 hv = hp[q];
                    asm("fma.rn.f32x2 %0, %1, %2, %0;" : "+l"(acc[2 * q])     : "l"(hv.x), "l"(wp));
                    asm("fma.rn.f32x2 %0, %1, %2, %0;" : "+l"(acc[2 * q + 1]) : "l"(hv.y), "l"(wp));
                }
                w = wn;
            }
        }
        // epilogue: relu(acc + b2) and accumulate over n
        #pragma unroll
        for (int p = 0; p < 32; p++) {
            unsigned int lu, hu;
            asm("mov.b64 {%0, %1}, %2;" : "=r"(lu), "=r"(hu) : "l"(acc[p]));
            float lo = __uint_as_float(lu), hi = __uint_as_float(hu);
            int bi = p >> 3;  // rows 2p,2p+1 share bi (16 n per b)
            S2a[bi] += fmaxf(lo + b2c, 0.f) + fmaxf(hi + b2c, 0.f);
        }
    }

    float* S2o = g_scratch + OFF_S2 + ((size_t)beta * BATCH + b0) * D2 + c;
    #pragma unroll
    for (int bi = 0; bi < S2_BT; bi++) S2o[(size_t)bi * D2] = S2a[bi];
}

// ---------------------------------------------------------------------------
// K5: out[r, c'] = (S2[r,:]/96) @ W3 + b3.  8 rows per block, 128 threads.
// r = beta*1024 + b, matching output layout (h_n then h_a).
// ---------------------------------------------------------------------------
__global__ void __launch_bounds__(128) k_final(
    const float* __restrict__ W3, const float* __restrict__ b3,
    float* __restrict__ out)
{
    __shared__ float s2s[8][D2];
    const int r0 = blockIdx.x * 8;
    const float* S2 = g_scratch + OFF_S2 + (size_t)r0 * D2;
    for (int i = threadIdx.x; i < 8 * D2; i += 128)
        s2s[i >> 8][i & 255] = S2[i];
    __syncthreads();
    const int c2 = threadIdx.x;
    float acc[8];
    #pragma unroll
    for (int p = 0; p < 8; p++) acc[p] = 0.f;
    for (int cc = 0; cc < D2; cc++) {
        float w3 = W3[(size_t)cc * D4 + c2];
        #pragma unroll
        for (int p = 0; p < 8; p++) acc[p] += s2s[p][cc] * w3;
    }
    const float bb = b3[c2];
    #pragma unroll
    for (int p = 0; p < 8; p++)
        out[(size_t)(r0 + p) * D4 + c2] = acc[p] * (1.f / 96.f) + bb;
}

// ---------------------------------------------------------------------------
extern "C" void kernel_launch(void* const* d_in, const int* in_sizes, int n_in,
                              void* d_out, int out_size)
{
    const float* img = (const float*)d_in[0];
    const float* tn  = (const float*)d_in[1];
    const float* ta  = (const float*)d_in[2];
    const float* ls  = (const float*)d_in[3];
    const float* W1  = (const float*)d_in[4];
    const float* b1  = (const float*)d_in[5];
    const float* W2  = (const float*)d_in[6];
    const float* b2  = (const float*)d_in[7];
    const float* W3  = (const float*)d_in[8];
    const float* b3  = (const float*)d_in[9];
    float* out = (float*)d_out;

    // E = exp(softmax(scale * img@text^T)) for both branches
    k_softmax<<<BATCH / 8, 256>>>(img, tn, ta, ls);
    // Pre = img @ W1[:512,:] + b1
    k_gemm<<<dim3(DIM / 64, BATCH / 64), 256>>>(img, W1, b1, OFF_PRE, BATCH, DIM, DIM);
    // T = text @ W1[512:,:]  (both branches)
    k_gemm<<<dim3(DIM / 64, 2), 256>>>(tn, W1 + DIM * DIM, nullptr, OFF_T, NN, DIM, DIM);
    k_gemm<<<dim3(DIM / 64, 2), 256>>>(ta, W1 + DIM * DIM, nullptr, OFF_T + NN * DIM, NN, DIM, DIM);
    // fused layer-1 construction + layer-2 GEMM + relu + sum over n
    k_step2<<<dim3(BATCH / S2_BT, 2), 256>>>(W2, b2);
    // layer 3 on the n-averaged representation
    k_final<<<(2 * BATCH) / 8, 128>>>(W3, b3, out);
}

// round 6
// speedup vs baseline: 2.8591x; 2.8591x over previous
#include <cuda_runtime.h>
#include <cstdint>

// Problem constants
#define BATCH 1024
#define NN 96
#define DIM 512
#define D2 256
#define D4 128

// Scratch layout
#define OFF_PRE 0                        // [1024][512]  img@W1_top + b1
#define OFF_T   (OFF_PRE + BATCH*DIM)    // [2][96][512] text@W1_bot
#define OFF_E   (OFF_T + 2*NN*DIM)       // [2][1024][96] exp(softmax(sims))
#define OFF_S2  (OFF_E + 2*BATCH*NN)     // [2][1024][256] sum_n relu(h1@W2+b2)
#define OFF_W2T (OFF_S2 + 2*BATCH*D2)    // [256][512] tf32(W2^T)
#define SCRATCH_TOTAL (OFF_W2T + DIM*D2)

__device__ float g_scratch[SCRATCH_TOTAL];

__device__ __forceinline__ uint32_t f2tf32(float f) {
    uint32_t u; asm("cvt.rna.tf32.f32 %0, %1;" : "=r"(u) : "f"(f)); return u;
}

// ---------------------------------------------------------------------------
// K1: softmax -> E = exp(softmax(scale * img@text^T))
// ---------------------------------------------------------------------------
__global__ void __launch_bounds__(256) k_softmax(
    const float* __restrict__ img, const float* __restrict__ tn,
    const float* __restrict__ ta, const float* __restrict__ ls)
{
    __shared__ float imgs[8][DIM];
    __shared__ float sims[8][192];
    const int b0 = blockIdx.x * 8;
    const int t = threadIdx.x;

    const float4* gi = (const float4*)(img + (size_t)b0 * DIM);
    float4* si = (float4*)&imgs[0][0];
    for (int i = t; i < 8 * (DIM / 4); i += 256) si[i] = gi[i];
    __syncthreads();

    const float scale = expf(ls[0]);

    if (t < 192) {
        const float* txt = (t < 96) ? (tn + (size_t)t * DIM) : (ta + (size_t)(t - 96) * DIM);
        const float4* tv = (const float4*)txt;
        float acc[8];
        #pragma unroll
        for (int bi = 0; bi < 8; bi++) acc[bi] = 0.f;
        for (int k = 0; k < DIM / 4; k++) {
            float4 x = tv[k];
            #pragma unroll
            for (int bi = 0; bi < 8; bi++) {
                float4 y = *(const float4*)&imgs[bi][k * 4];
                acc[bi] += x.x * y.x + x.y * y.y + x.z * y.z + x.w * y.w;
            }
        }
        #pragma unroll
        for (int bi = 0; bi < 8; bi++) sims[bi][t] = acc[bi] * scale;
    }
    __syncthreads();

    const int w = t >> 5, lane = t & 31;
    const int b = b0 + w;
    #pragma unroll
    for (int br = 0; br < 2; br++) {
        float v0 = sims[w][br * 96 + lane];
        float v1 = sims[w][br * 96 + lane + 32];
        float v2 = sims[w][br * 96 + lane + 64];
        float m = fmaxf(v0, fmaxf(v1, v2));
        #pragma unroll
        for (int off = 16; off > 0; off >>= 1)
            m = fmaxf(m, __shfl_xor_sync(0xffffffffu, m, off));
        float e0 = expf(v0 - m), e1 = expf(v1 - m), e2 = expf(v2 - m);
        float s = e0 + e1 + e2;
        #pragma unroll
        for (int off = 16; off > 0; off >>= 1)
            s += __shfl_xor_sync(0xffffffffu, s, off);
        float inv = 1.f / s;
        float* Eo = g_scratch + OFF_E + ((size_t)br * BATCH + b) * NN;
        Eo[lane]      = expf(e0 * inv);
        Eo[lane + 32] = expf(e1 * inv);
        Eo[lane + 64] = expf(e2 * inv);
    }
}

// ---------------------------------------------------------------------------
// K2: generic fp32 GEMM (Pre, T)
// ---------------------------------------------------------------------------
__global__ void __launch_bounds__(256) k_gemm(
    const float* __restrict__ A, const float* __restrict__ Bm,
    const float* __restrict__ bias, int coff, int M, int N, int K)
{
    __shared__ float As[16][64];
    __shared__ float Bs[16][64];
    float* C = g_scratch + coff;
    const int n0 = blockIdx.x * 64, m0 = blockIdx.y * 64;
    const int t = threadIdx.x;
    const int tx = t & 15, ty = t >> 4;

    float acc[4][4];
    #pragma unroll
    for (int i = 0; i < 4; i++)
        #pragma unroll
        for (int j = 0; j < 4; j++) acc[i][j] = 0.f;

    for (int k0 = 0; k0 < K; k0 += 16) {
        __syncthreads();
        {
            int aRow = t >> 2, aCol = (t & 3) * 4;
            float4 v = make_float4(0.f, 0.f, 0.f, 0.f);
            if (m0 + aRow < M)
                v = *(const float4*)&A[(size_t)(m0 + aRow) * K + k0 + aCol];
            As[aCol][aRow] = v.x; As[aCol + 1][aRow] = v.y;
            As[aCol + 2][aRow] = v.z; As[aCol + 3][aRow] = v.w;
            int bRow = t >> 4, bCol = (t & 15) * 4;
            float4 wv = *(const float4*)&Bm[(size_t)(k0 + bRow) * N + n0 + bCol];
            *(float4*)&Bs[bRow][bCol] = wv;
        }
        __syncthreads();
        #pragma unroll
        for (int kk = 0; kk < 16; kk++) {
            float4 a = *(const float4*)&As[kk][ty * 4];
            float4 bq = *(const float4*)&Bs[kk][tx * 4];
            float av[4] = {a.x, a.y, a.z, a.w};
            float bv[4] = {bq.x, bq.y, bq.z, bq.w};
            #pragma unroll
            for (int i = 0; i < 4; i++)
                #pragma unroll
                for (int j = 0; j < 4; j++) acc[i][j] += av[i] * bv[j];
        }
    }
    #pragma unroll
    for (int i = 0; i < 4; i++) {
        int m = m0 + ty * 4 + i;
        if (m < M) {
            #pragma unroll
            for (int j = 0; j < 4; j++) {
                int n = n0 + tx * 4 + j;
                float bb = bias ? bias[n] : 0.f;
                C[(size_t)m * N + n] = acc[i][j] + bb;
            }
        }
    }
}

// ---------------------------------------------------------------------------
// K3: prep — W2T[n][k] = tf32(W2[k][n]) and zero S2
// ---------------------------------------------------------------------------
__global__ void __launch_bounds__(256) k_prep(const float* __restrict__ W2)
{
    int i = blockIdx.x * 256 + threadIdx.x;
    if (i < DIM * D2) {
        int n = i >> 9, k = i & 511;
        float v = W2[(size_t)k * D2 + n];
        g_scratch[OFF_W2T + i] = __uint_as_float(f2tf32(v));
    }
    if (i < 2 * BATCH * D2) g_scratch[OFF_S2 + i] = 0.f;
}

// ---------------------------------------------------------------------------
// K4: warp-level tf32 mma.sync kernel (sm_103 baseline target; no tcgen05).
// Block: 128 rows x 256 cols, K=512 in 32-wide SMEM chunks.
//   A = h1 built on the fly: tf32(relu(Pre[b] + e[b,n]*T[n])), As[128][36]
//   B = W2T (pre-rounded tf32), Bs[256][36]
// 8 warps = 4(M) x 2(N); warp tile 32x128 = 2 mfrag x 16 nfrag of m16n8k8.
// 128-row tiles always split batch on a multiple-of-32 row, so each warp's
// 32 rows share one b -> full shuffle row-reduce, then atomicAdd into S2.
// ---------------------------------------------------------------------------
#define AS_N 36
#define SMEM_FLOATS (128 * AS_N + 256 * AS_N + 256)

__global__ void __launch_bounds__(256, 1) k_mma(const float* __restrict__ b2)
{
    extern __shared__ __align__(16) float smem[];
    float* As  = smem;                    // [128][36]
    float* Bs  = smem + 128 * AS_N;       // [256][36]
    float* b2s = Bs + 256 * AS_N;         // [256]

    const int t = threadIdx.x, lane = t & 31, wid = t >> 5;
    const int warpM = wid & 3, warpN = wid >> 2;
    const int g = lane >> 2, tig = lane & 3;
    const int tile = blockIdx.x, beta = blockIdx.y;

    b2s[t] = b2[t];

    // A-fill row constants (2 threads per row)
    const int rowA = t >> 1, half = t & 1;
    const int r = tile * 128 + rowA;
    const int bbA = r / 96, nidx = r - bbA * 96;
    const float ev = g_scratch[OFF_E + ((size_t)beta * BATCH + bbA) * NN + nidx];
    const float* pPre = g_scratch + OFF_PRE + (size_t)bbA * DIM + half * 16;
    const float* pT   = g_scratch + OFF_T + ((size_t)beta * NN + nidx) * DIM + half * 16;
    const float* pW2T = g_scratch + OFF_W2T + (size_t)t * DIM;   // B row n = t

    float acc[2][16][4];
    #pragma unroll
    for (int mf = 0; mf < 2; mf++)
        #pragma unroll
        for (int nf = 0; nf < 16; nf++)
            #pragma unroll
            for (int q = 0; q < 4; q++) acc[mf][nf][q] = 0.f;

    for (int k0 = 0; k0 < DIM; k0 += 32) {
        __syncthreads();
        // A chunk: h1 = tf32(relu(Pre + ev*T)), 16 elems per thread
        #pragma unroll
        for (int gi = 0; gi < 4; gi++) {
            float4 P  = *(const float4*)(pPre + k0 + gi * 4);
            float4 Tv = *(const float4*)(pT + k0 + gi * 4);
            float4 o;
            o.x = __uint_as_float(f2tf32(fmaxf(fmaf(ev, Tv.x, P.x), 0.f)));
            o.y = __uint_as_float(f2tf32(fmaxf(fmaf(ev, Tv.y, P.y), 0.f)));
            o.z = __uint_as_float(f2tf32(fmaxf(fmaf(ev, Tv.z, P.z), 0.f)));
            o.w = __uint_as_float(f2tf32(fmaxf(fmaf(ev, Tv.w, P.w), 0.f)));
            *(float4*)(As + (size_t)rowA * AS_N + half * 16 + gi * 4) = o;
        }
        // B chunk: 32 elems per thread (row n = t)
        #pragma unroll
        for (int gi = 0; gi < 8; gi++) {
            float4 w = *(const float4*)(pW2T + k0 + gi * 4);
            *(float4*)(Bs + (size_t)t * AS_N + gi * 4) = w;
        }
        __syncthreads();

        #pragma unroll
        for (int ks = 0; ks < 4; ks++) {
            const int koff = ks * 8;
            uint32_t afr[2][4];
            #pragma unroll
            for (int mf = 0; mf < 2; mf++) {
                const float* ap = As + (size_t)(warpM * 32 + mf * 16 + g) * AS_N + koff + tig;
                afr[mf][0] = __float_as_uint(ap[0]);
                afr[mf][1] = __float_as_uint(ap[8 * AS_N]);
                afr[mf][2] = __float_as_uint(ap[4]);
                afr[mf][3] = __float_as_uint(ap[8 * AS_N + 4]);
            }
            #pragma unroll
            for (int nf = 0; nf < 16; nf++) {
                const float* bp = Bs + (size_t)(warpN * 128 + nf * 8 + g) * AS_N + koff + tig;
                uint32_t b0 = __float_as_uint(bp[0]);
                uint32_t b1 = __float_as_uint(bp[4]);
                #pragma unroll
                for (int mf = 0; mf < 2; mf++) {
                    asm volatile(
                        "mma.sync.aligned.m16n8k8.row.col.f32.tf32.tf32.f32 "
                        "{%0,%1,%2,%3}, {%4,%5,%6,%7}, {%8,%9}, {%0,%1,%2,%3};"
                        : "+f"(acc[mf][nf][0]), "+f"(acc[mf][nf][1]),
                          "+f"(acc[mf][nf][2]), "+f"(acc[mf][nf][3])
                        : "r"(afr[mf][0]), "r"(afr[mf][1]), "r"(afr[mf][2]), "r"(afr[mf][3]),
                          "r"(b0), "r"(b1));
                }
            }
        }
    }

    // Epilogue: relu(acc + b2), reduce this warp's 32 rows (single b), RED to S2
    const int bw = (tile * 128 + warpM * 32) / 96;
    float* S2p = g_scratch + OFF_S2 + ((size_t)beta * BATCH + bw) * D2;
    #pragma unroll
    for (int nf = 0; nf < 16; nf++) {
        const int colE = warpN * 128 + nf * 8 + 2 * tig;
        const float be = b2s[colE], bo = b2s[colE + 1];
        float ve = 0.f, vo = 0.f;
        #pragma unroll
        for (int mf = 0; mf < 2; mf++) {
            ve += fmaxf(acc[mf][nf][0] + be, 0.f) + fmaxf(acc[mf][nf][2] + be, 0.f);
            vo += fmaxf(acc[mf][nf][1] + bo, 0.f) + fmaxf(acc[mf][nf][3] + bo, 0.f);
        }
        #pragma unroll
        for (int m = 4; m <= 16; m <<= 1) {
            ve += __shfl_xor_sync(0xffffffffu, ve, m);
            vo += __shfl_xor_sync(0xffffffffu, vo, m);
        }
        if (g == 0) {
            atomicAdd(S2p + colE, ve);
            atomicAdd(S2p + colE + 1, vo);
        }
    }
}

// ---------------------------------------------------------------------------
// K5: out = (S2/96) @ W3 + b3
// ---------------------------------------------------------------------------
__global__ void __launch_bounds__(128) k_final(
    const float* __restrict__ W3, const float* __restrict__ b3,
    float* __restrict__ out)
{
    __shared__ float s2s[8][D2];
    const int r0 = blockIdx.x * 8;
    const float* S2 = g_scratch + OFF_S2 + (size_t)r0 * D2;
    for (int i = threadIdx.x; i < 8 * D2; i += 128)
        s2s[i >> 8][i & 255] = S2[i];
    __syncthreads();
    const int c2 = threadIdx.x;
    float acc[8];
    #pragma unroll
    for (int p = 0; p < 8; p++) acc[p] = 0.f;
    for (int cc = 0; cc < D2; cc++) {
        float w3 = W3[(size_t)cc * D4 + c2];
        #pragma unroll
        for (int p = 0; p < 8; p++) acc[p] += s2s[p][cc] * w3;
    }
    const float bb = b3[c2];
    #pragma unroll
    for (int p = 0; p < 8; p++)
        out[(size_t)(r0 + p) * D4 + c2] = acc[p] * (1.f / 96.f) + bb;
}

// ---------------------------------------------------------------------------
extern "C" void kernel_launch(void* const* d_in, const int* in_sizes, int n_in,
                              void* d_out, int out_size)
{
    const float* img = (const float*)d_in[0];
    const float* tn  = (const float*)d_in[1];
    const float* ta  = (const float*)d_in[2];
    const float* ls  = (const float*)d_in[3];
    const float* W1  = (const float*)d_in[4];
    const float* b1  = (const float*)d_in[5];
    const float* W2  = (const float*)d_in[6];
    const float* b2  = (const float*)d_in[7];
    const float* W3  = (const float*)d_in[8];
    const float* b3  = (const float*)d_in[9];
    float* out = (float*)d_out;

    cudaFuncSetAttribute(k_mma, cudaFuncAttributeMaxDynamicSharedMemorySize,
                         SMEM_FLOATS * 4);

    k_softmax<<<BATCH / 8, 256>>>(img, tn, ta, ls);
    k_gemm<<<dim3(DIM / 64, BATCH / 64), 256>>>(img, W1, b1, OFF_PRE, BATCH, DIM, DIM);
    k_gemm<<<dim3(DIM / 64, 2), 256>>>(tn, W1 + DIM * DIM, nullptr, OFF_T, NN, DIM, DIM);
    k_gemm<<<dim3(DIM / 64, 2), 256>>>(ta, W1 + DIM * DIM, nullptr, OFF_T + NN * DIM, NN, DIM, DIM);
    k_prep<<<(2 * BATCH * D2) / 256, 256>>>(W2);
    k_mma<<<dim3(98304 / 128, 2), 256, SMEM_FLOATS * 4>>>(b2);
    k_final<<<(2 * BATCH) / 8, 128>>>(W3, b3, out);
}

// round 8
// speedup vs baseline: 4.6547x; 1.6281x over previous
#include <cuda_runtime.h>
#include <cuda_fp16.h>
#include <cstdint>

// Problem constants
#define BATCH 1024
#define NN 96
#define DIM 512
#define D2 256
#define D4 128

// Scratch layout (floats; W2H region reinterpreted as half)
#define OFF_PRE 0                        // [1024][512]  img@W1_top + b1
#define OFF_T   (OFF_PRE + BATCH*DIM)    // [2][96][512] text@W1_bot
#define OFF_E   (OFF_T + 2*NN*DIM)       // [2][1024][96] exp(softmax(sims))
#define OFF_S2  (OFF_E + 2*BATCH*NN)     // [2][1024][256] sum_n relu(h1@W2+b2)
#define OFF_W2T (OFF_S2 + 2*BATCH*D2)    // half[256][512] = fp16(W2^T)
#define SCRATCH_TOTAL (OFF_W2T + DIM*D2)

__device__ float g_scratch[SCRATCH_TOTAL];

__device__ __forceinline__ uint32_t smem_u32(const void* p) {
    uint32_t a;
    asm("{ .reg .u64 t; cvta.to.shared.u64 t, %1; cvt.u32.u64 %0, t; }"
        : "=r"(a) : "l"(p));
    return a;
}
__device__ __forceinline__ uint32_t packh2(float x, float y) {
    __half2 h = __floats2half2_rn(x, y);
    return *(uint32_t*)&h;
}

#define LDSM_X4(r0, r1, r2, r3, addr) \
    asm volatile("ldmatrix.sync.aligned.m8n8.x4.shared.b16 {%0,%1,%2,%3}, [%4];" \
        : "=r"(r0), "=r"(r1), "=r"(r2), "=r"(r3) : "r"(addr))

#define MMA_F16(c, a, b0, b1) \
    asm volatile("mma.sync.aligned.m16n8k16.row.col.f32.f16.f16.f32 " \
        "{%0,%1,%2,%3}, {%4,%5,%6,%7}, {%8,%9}, {%0,%1,%2,%3};" \
        : "+f"((c)[0]), "+f"((c)[1]), "+f"((c)[2]), "+f"((c)[3]) \
        : "r"((a)[0]), "r"((a)[1]), "r"((a)[2]), "r"((a)[3]), "r"(b0), "r"(b1))

#define CP_ASYNC16(dst, src) \
    asm volatile("cp.async.ca.shared.global [%0], [%1], 16;" :: "r"(dst), "l"(src) : "memory")

// ---------------------------------------------------------------------------
// K1: softmax -> E = exp(softmax(scale * img@text^T))
// ---------------------------------------------------------------------------
__global__ void __launch_bounds__(256) k_softmax(
    const float* __restrict__ img, const float* __restrict__ tn,
    const float* __restrict__ ta, const float* __restrict__ ls)
{
    __shared__ float imgs[8][DIM];
    __shared__ float sims[8][192];
    const int b0 = blockIdx.x * 8;
    const int t = threadIdx.x;

    const float4* gi = (const float4*)(img + (size_t)b0 * DIM);
    float4* si = (float4*)&imgs[0][0];
    for (int i = t; i < 8 * (DIM / 4); i += 256) si[i] = gi[i];
    __syncthreads();

    const float scale = expf(ls[0]);

    if (t < 192) {
        const float* txt = (t < 96) ? (tn + (size_t)t * DIM) : (ta + (size_t)(t - 96) * DIM);
        const float4* tv = (const float4*)txt;
        float acc[8];
        #pragma unroll
        for (int bi = 0; bi < 8; bi++) acc[bi] = 0.f;
        for (int k = 0; k < DIM / 4; k++) {
            float4 x = tv[k];
            #pragma unroll
            for (int bi = 0; bi < 8; bi++) {
                float4 y = *(const float4*)&imgs[bi][k * 4];
                acc[bi] += x.x * y.x + x.y * y.y + x.z * y.z + x.w * y.w;
            }
        }
        #pragma unroll
        for (int bi = 0; bi < 8; bi++) sims[bi][t] = acc[bi] * scale;
    }
    __syncthreads();

    const int w = t >> 5, lane = t & 31;
    const int b = b0 + w;
    #pragma unroll
    for (int br = 0; br < 2; br++) {
        float v0 = sims[w][br * 96 + lane];
        float v1 = sims[w][br * 96 + lane + 32];
        float v2 = sims[w][br * 96 + lane + 64];
        float m = fmaxf(v0, fmaxf(v1, v2));
        #pragma unroll
        for (int off = 16; off > 0; off >>= 1)
            m = fmaxf(m, __shfl_xor_sync(0xffffffffu, m, off));
        float e0 = expf(v0 - m), e1 = expf(v1 - m), e2 = expf(v2 - m);
        float s = e0 + e1 + e2;
        #pragma unroll
        for (int off = 16; off > 0; off >>= 1)
            s += __shfl_xor_sync(0xffffffffu, s, off);
        float inv = 1.f / s;
        float* Eo = g_scratch + OFF_E + ((size_t)br * BATCH + b) * NN;
        Eo[lane]      = expf(e0 * inv);
        Eo[lane + 32] = expf(e1 * inv);
        Eo[lane + 64] = expf(e2 * inv);
    }
}

// ---------------------------------------------------------------------------
// K2: generic fp32 GEMM (Pre, T)
// ---------------------------------------------------------------------------
__global__ void __launch_bounds__(256) k_gemm(
    const float* __restrict__ A, const float* __restrict__ Bm,
    const float* __restrict__ bias, int coff, int M, int N, int K)
{
    __shared__ float As[16][64];
    __shared__ float Bs[16][64];
    float* C = g_scratch + coff;
    const int n0 = blockIdx.x * 64, m0 = blockIdx.y * 64;
    const int t = threadIdx.x;
    const int tx = t & 15, ty = t >> 4;

    float acc[4][4];
    #pragma unroll
    for (int i = 0; i < 4; i++)
        #pragma unroll
        for (int j = 0; j < 4; j++) acc[i][j] = 0.f;

    for (int k0 = 0; k0 < K; k0 += 16) {
        __syncthreads();
        {
            int aRow = t >> 2, aCol = (t & 3) * 4;
            float4 v = make_float4(0.f, 0.f, 0.f, 0.f);
            if (m0 + aRow < M)
                v = *(const float4*)&A[(size_t)(m0 + aRow) * K + k0 + aCol];
            As[aCol][aRow] = v.x; As[aCol + 1][aRow] = v.y;
            As[aCol + 2][aRow] = v.z; As[aCol + 3][aRow] = v.w;
            int bRow = t >> 4, bCol = (t & 15) * 4;
            float4 wv = *(const float4*)&Bm[(size_t)(k0 + bRow) * N + n0 + bCol];
            *(float4*)&Bs[bRow][bCol] = wv;
        }
        __syncthreads();
        #pragma unroll
        for (int kk = 0; kk < 16; kk++) {
            float4 a = *(const float4*)&As[kk][ty * 4];
            float4 bq = *(const float4*)&Bs[kk][tx * 4];
            float av[4] = {a.x, a.y, a.z, a.w};
            float bv[4] = {bq.x, bq.y, bq.z, bq.w};
            #pragma unroll
            for (int i = 0; i < 4; i++)
                #pragma unroll
                for (int j = 0; j < 4; j++) acc[i][j] += av[i] * bv[j];
        }
    }
    #pragma unroll
    for (int i = 0; i < 4; i++) {
        int m = m0 + ty * 4 + i;
        if (m < M) {
            #pragma unroll
            for (int j = 0; j < 4; j++) {
                int n = n0 + tx * 4 + j;
                float bb = bias ? bias[n] : 0.f;
                C[(size_t)m * N + n] = acc[i][j] + bb;
            }
        }
    }
}

// ---------------------------------------------------------------------------
// K3: prep — W2H[n][k] = fp16(W2[k][n]) and zero S2
// ---------------------------------------------------------------------------
__global__ void __launch_bounds__(256) k_prep(const float* __restrict__ W2)
{
    int i = blockIdx.x * 256 + threadIdx.x;
    if (i < DIM * D2) {
        int n = i >> 9, k = i & 511;
        __half* W2H = (__half*)(g_scratch + OFF_W2T);
        W2H[i] = __float2half(W2[(size_t)k * D2 + n]);
    }
    if (i < 2 * BATCH * D2) g_scratch[OFF_S2 + i] = 0.f;
}

// ---------------------------------------------------------------------------
// K4: fp16 mma.sync m16n8k16 kernel, double-buffered (cp.async B, reg-prefetch A).
// Block: 128 rows x 256 cols, K=512 in 32-wide chunks.
//   A = h1 on the fly: fp16(relu(Pre[b] + e[b,n]*T[n])), As[2][128][40] half
//   B = W2H (pre-converted), Bs[2][256][40] half
// 8 warps = 4(M) x 2(N); warp tile 32x128 = 2 mf x 16 nf.
// Each warp's 32 rows share one batch b (tiles split on 32-row boundaries) ->
// shuffle row-reduce, atomicAdd into S2.
// ---------------------------------------------------------------------------
#define ASTR 40                       // half stride (80 B)
#define SMA (128 * ASTR * 2)          // bytes per A buffer (10240)
#define SMB (256 * ASTR * 2)          // bytes per B buffer (20480)
#define OFF_AS0 0
#define OFF_AS1 SMA
#define OFF_BS0 (2 * SMA)
#define OFF_BS1 (2 * SMA + SMB)
#define OFF_B2S (2 * SMA + 2 * SMB)
#define SMEM_BYTES (OFF_B2S + 1024)

__global__ void __launch_bounds__(256, 1) k_mma(const float* __restrict__ b2)
{
    extern __shared__ __align__(16) char smem[];
    const uint32_t sb = smem_u32(smem);
    float* b2s = (float*)(smem + OFF_B2S);

    const int t = threadIdx.x, lane = t & 31, wid = t >> 5;
    const int warpM = wid & 3, warpN = wid >> 2;
    const int g = lane >> 2, tig = lane & 3;
    const int tile = blockIdx.x, beta = blockIdx.y;

    b2s[t] = b2[t];

    // A-fill constants: 2 threads per row
    const int rowA = t >> 1, halfk = (t & 1) * 16;
    const int r = tile * 128 + rowA;
    const int bbA = r / 96, nidx = r - bbA * 96;
    const float ev = g_scratch[OFF_E + ((size_t)beta * BATCH + bbA) * NN + nidx];
    const float* pPre = g_scratch + OFF_PRE + (size_t)bbA * DIM + halfk;
    const float* pT   = g_scratch + OFF_T + ((size_t)beta * NN + nidx) * DIM + halfk;
    const __half* W2H = (const __half*)(g_scratch + OFF_W2T);
    const __half* pB  = W2H + (size_t)t * DIM;          // B row n = t
    const uint32_t aStAddr = sb + (uint32_t)(rowA * ASTR + halfk) * 2;
    const uint32_t bStAddr = sb + OFF_BS0 + (uint32_t)(t * ASTR) * 2;

    // ldmatrix addresses (per-buffer offsets added in loop)
    const uint32_t aLdBase = sb + (uint32_t)(((warpM * 32 + (lane & 15)) * ASTR
                              + ((lane >> 4) * 8)) * 2);
    const uint32_t bLdBase = sb + OFF_BS0 + (uint32_t)(((warpN * 128 + ((lane >> 4) * 8) + (lane & 7)) * ASTR
                              + (((lane >> 3) & 1) * 8)) * 2);

    float acc[2][16][4];
    #pragma unroll
    for (int mf = 0; mf < 2; mf++)
        #pragma unroll
        for (int nf = 0; nf < 16; nf++)
            #pragma unroll
            for (int q = 0; q < 4; q++) acc[mf][nf][q] = 0.f;

    // ---- prologue: fill chunk 0 into buffer 0
    {
        #pragma unroll
        for (int gi = 0; gi < 4; gi++)
            CP_ASYNC16(bStAddr + gi * 16, (const char*)(pB) + gi * 16);
        asm volatile("cp.async.commit_group;" ::: "memory");
        float4 pa0 = ((const float4*)pPre)[0], pa1 = ((const float4*)pPre)[1];
        float4 pa2 = ((const float4*)pPre)[2], pa3 = ((const float4*)pPre)[3];
        float4 ta0 = ((const float4*)pT)[0],  ta1 = ((const float4*)pT)[1];
        float4 ta2 = ((const float4*)pT)[2],  ta3 = ((const float4*)pT)[3];
        uint32_t u[8];
        u[0] = packh2(fmaxf(fmaf(ev, ta0.x, pa0.x), 0.f), fmaxf(fmaf(ev, ta0.y, pa0.y), 0.f));
        u[1] = packh2(fmaxf(fmaf(ev, ta0.z, pa0.z), 0.f), fmaxf(fmaf(ev, ta0.w, pa0.w), 0.f));
        u[2] = packh2(fmaxf(fmaf(ev, ta1.x, pa1.x), 0.f), fmaxf(fmaf(ev, ta1.y, pa1.y), 0.f));
        u[3] = packh2(fmaxf(fmaf(ev, ta1.z, pa1.z), 0.f), fmaxf(fmaf(ev, ta1.w, pa1.w), 0.f));
        u[4] = packh2(fmaxf(fmaf(ev, ta2.x, pa2.x), 0.f), fmaxf(fmaf(ev, ta2.y, pa2.y), 0.f));
        u[5] = packh2(fmaxf(fmaf(ev, ta2.z, pa2.z), 0.f), fmaxf(fmaf(ev, ta2.w, pa2.w), 0.f));
        u[6] = packh2(fmaxf(fmaf(ev, ta3.x, pa3.x), 0.f), fmaxf(fmaf(ev, ta3.y, pa3.y), 0.f));
        u[7] = packh2(fmaxf(fmaf(ev, ta3.z, pa3.z), 0.f), fmaxf(fmaf(ev, ta3.w, pa3.w), 0.f));
        asm volatile("st.shared.v4.b32 [%0], {%1,%2,%3,%4};"
                     :: "r"(aStAddr), "r"(u[0]), "r"(u[1]), "r"(u[2]), "r"(u[3]) : "memory");
        asm volatile("st.shared.v4.b32 [%0], {%1,%2,%3,%4};"
                     :: "r"(aStAddr + 16), "r"(u[4]), "r"(u[5]), "r"(u[6]), "r"(u[7]) : "memory");
        asm volatile("cp.async.wait_group 0;" ::: "memory");
    }
    __syncthreads();

    for (int c = 0; c < 16; c++) {
        const int p = c & 1, q = 1 - p;
        const bool nxt = (c + 1 < 16);
        float4 pa0, pa1, pa2, pa3, ta0, ta1, ta2, ta3;

        if (nxt) {
            const int k1 = (c + 1) * 32;
            // B chunk c+1 via cp.async into buffer q
            #pragma unroll
            for (int gi = 0; gi < 4; gi++)
                CP_ASYNC16(bStAddr + q * SMB + gi * 16, (const char*)(pB + k1) + gi * 16);
            asm volatile("cp.async.commit_group;" ::: "memory");
            // A inputs chunk c+1 into registers
            pa0 = ((const float4*)(pPre + k1))[0]; pa1 = ((const float4*)(pPre + k1))[1];
            pa2 = ((const float4*)(pPre + k1))[2]; pa3 = ((const float4*)(pPre + k1))[3];
            ta0 = ((const float4*)(pT + k1))[0];   ta1 = ((const float4*)(pT + k1))[1];
            ta2 = ((const float4*)(pT + k1))[2];   ta3 = ((const float4*)(pT + k1))[3];
        }

        // ---- MMA on chunk c (buffer p)
        const uint32_t aB = aLdBase + p * SMA;
        const uint32_t bB = bLdBase + p * SMB;
        #pragma unroll
        for (int ks = 0; ks < 2; ks++) {
            uint32_t af[2][4];
            #pragma unroll
            for (int mf = 0; mf < 2; mf++)
                LDSM_X4(af[mf][0], af[mf][1], af[mf][2], af[mf][3],
                        aB + (uint32_t)((mf * 16 * ASTR + ks * 16) * 2));
            #pragma unroll
            for (int nf2 = 0; nf2 < 8; nf2++) {
                uint32_t b0, b1, b2r, b3r;
                LDSM_X4(b0, b1, b2r, b3r,
                        bB + (uint32_t)((nf2 * 16 * ASTR + ks * 16) * 2));
                #pragma unroll
                for (int mf = 0; mf < 2; mf++) {
                    MMA_F16(acc[mf][2 * nf2],     af[mf], b0, b1);
                    MMA_F16(acc[mf][2 * nf2 + 1], af[mf], b2r, b3r);
                }
            }
        }

        if (nxt) {
            uint32_t u[8];
            u[0] = packh2(fmaxf(fmaf(ev, ta0.x, pa0.x), 0.f), fmaxf(fmaf(ev, ta0.y, pa0.y), 0.f));
            u[1] = packh2(fmaxf(fmaf(ev, ta0.z, pa0.z), 0.f), fmaxf(fmaf(ev, ta0.w, pa0.w), 0.f));
            u[2] = packh2(fmaxf(fmaf(ev, ta1.x, pa1.x), 0.f), fmaxf(fmaf(ev, ta1.y, pa1.y), 0.f));
            u[3] = packh2(fmaxf(fmaf(ev, ta1.z, pa1.z), 0.f), fmaxf(fmaf(ev, ta1.w, pa1.w), 0.f));
            u[4] = packh2(fmaxf(fmaf(ev, ta2.x, pa2.x), 0.f), fmaxf(fmaf(ev, ta2.y, pa2.y), 0.f));
            u[5] = packh2(fmaxf(fmaf(ev, ta2.z, pa2.z), 0.f), fmaxf(fmaf(ev, ta2.w, pa2.w), 0.f));
            u[6] = packh2(fmaxf(fmaf(ev, ta3.x, pa3.x), 0.f), fmaxf(fmaf(ev, ta3.y, pa3.y), 0.f));
            u[7] = packh2(fmaxf(fmaf(ev, ta3.z, pa3.z), 0.f), fmaxf(fmaf(ev, ta3.w, pa3.w), 0.f));
            const uint32_t ad = aStAddr + q * SMA;
            asm volatile("st.shared.v4.b32 [%0], {%1,%2,%3,%4};"
                         :: "r"(ad), "r"(u[0]), "r"(u[1]), "r"(u[2]), "r"(u[3]) : "memory");
            asm volatile("st.shared.v4.b32 [%0], {%1,%2,%3,%4};"
                         :: "r"(ad + 16), "r"(u[4]), "r"(u[5]), "r"(u[6]), "r"(u[7]) : "memory");
            asm volatile("cp.async.wait_group 0;" ::: "memory");
            __syncthreads();
        }
    }

    // Epilogue: relu(acc + b2), reduce this warp's 32 rows (single b), RED to S2
    const int bw = (tile * 128 + warpM * 32) / 96;
    float* S2p = g_scratch + OFF_S2 + ((size_t)beta * BATCH + bw) * D2;
    #pragma unroll
    for (int nf = 0; nf < 16; nf++) {
        const int colE = warpN * 128 + nf * 8 + 2 * tig;
        const float be = b2s[colE], bo = b2s[colE + 1];
        float ve = 0.f, vo = 0.f;
        #pragma unroll
        for (int mf = 0; mf < 2; mf++) {
            ve += fmaxf(acc[mf][nf][0] + be, 0.f) + fmaxf(acc[mf][nf][2] + be, 0.f);
            vo += fmaxf(acc[mf][nf][1] + bo, 0.f) + fmaxf(acc[mf][nf][3] + bo, 0.f);
        }
        #pragma unroll
        for (int m = 4; m <= 16; m <<= 1) {
            ve += __shfl_xor_sync(0xffffffffu, ve, m);
            vo += __shfl_xor_sync(0xffffffffu, vo, m);
        }
        if (g == 0) {
            atomicAdd(S2p + colE, ve);
            atomicAdd(S2p + colE + 1, vo);
        }
    }
}

// ---------------------------------------------------------------------------
// K5: out = (S2/96) @ W3 + b3
// ---------------------------------------------------------------------------
__global__ void __launch_bounds__(128) k_final(
    const float* __restrict__ W3, const float* __restrict__ b3,
    float* __restrict__ out)
{
    __shared__ float s2s[8][D2];
    const int r0 = blockIdx.x * 8;
    const float* S2 = g_scratch + OFF_S2 + (size_t)r0 * D2;
    for (int i = threadIdx.x; i < 8 * D2; i += 128)
        s2s[i >> 8][i & 255] = S2[i];
    __syncthreads();
    const int c2 = threadIdx.x;
    float acc[8];
    #pragma unroll
    for (int p = 0; p < 8; p++) acc[p] = 0.f;
    for (int cc = 0; cc < D2; cc++) {
        float w3 = W3[(size_t)cc * D4 + c2];
        #pragma unroll
        for (int p = 0; p < 8; p++) acc[p] += s2s[p][cc] * w3;
    }
    const float bb = b3[c2];
    #pragma unroll
    for (int p = 0; p < 8; p++)
        out[(size_t)(r0 + p) * D4 + c2] = acc[p] * (1.f / 96.f) + bb;
}

// ---------------------------------------------------------------------------
extern "C" void kernel_launch(void* const* d_in, const int* in_sizes, int n_in,
                              void* d_out, int out_size)
{
    const float* img = (const float*)d_in[0];
    const float* tn  = (const float*)d_in[1];
    const float* ta  = (const float*)d_in[2];
    const float* ls  = (const float*)d_in[3];
    const float* W1  = (const float*)d_in[4];
    const float* b1  = (const float*)d_in[5];
    const float* W2  = (const float*)d_in[6];
    const float* b2  = (const float*)d_in[7];
    const float* W3  = (const float*)d_in[8];
    const float* b3  = (const float*)d_in[9];
    float* out = (float*)d_out;

    cudaFuncSetAttribute(k_mma, cudaFuncAttributeMaxDynamicSharedMemorySize, SMEM_BYTES);

    k_softmax<<<BATCH / 8, 256>>>(img, tn, ta, ls);
    k_gemm<<<dim3(DIM / 64, BATCH / 64), 256>>>(img, W1, b1, OFF_PRE, BATCH, DIM, DIM);
    k_gemm<<<dim3(DIM / 64, 2), 256>>>(tn, W1 + DIM * DIM, nullptr, OFF_T, NN, DIM, DIM);
    k_gemm<<<dim3(DIM / 64, 2), 256>>>(ta, W1 + DIM * DIM, nullptr, OFF_T + NN * DIM, NN, DIM, DIM);
    k_prep<<<(2 * BATCH * D2) / 256, 256>>>(W2);
    k_mma<<<dim3(98304 / 128, 2), 256, SMEM_BYTES>>>(b2);
    k_final<<<(2 * BATCH) / 8, 128>>>(W3, b3, out);
}